// round 1
// baseline (speedup 1.0000x reference)
#include <cuda_runtime.h>

// FerroelectricBasisConv2d — GB300 sm_103a
// Simplified math (stop_gradient makes is_moving_up == 0.5):
//   g  = tanh(5x + 5Ec)
//   u  = k*x + 0.9*k*Ec + 0.1*k*Ec*g
//   out = sum( Ps*coef * tanh(u) ) + sum(bias*coef) + out_bias
// Shapes: x (4,16,32,32); params (32,16,3,3,3); out (4,32,32,32)

#define CIN     16
#define COUT    32
#define HW      32
#define NT      432          // CIN * 3 * 9
#define TILE_H  8
#define TILE_W  16
#define RG_H    10           // TILE_H + 2 halo
#define RG_W    18           // TILE_W + 2 halo
#define THREADS 128

__device__ __forceinline__ float tanh_fast(float x) {
    float r; asm("tanh.approx.f32 %0, %1;" : "=f"(r) : "f"(x)); return r;
}
__device__ __forceinline__ float ex2_fast(float x) {
    float r; asm("ex2.approx.f32 %0, %1;" : "=f"(r) : "f"(x)); return r;
}
__device__ __forceinline__ float rcp_fast(float x) {
    float r; asm("rcp.approx.f32 %0, %1;" : "=f"(r) : "f"(x)); return r;
}
// accurate tanh: 1 - 2/(exp(2u)+1), EX2 + RCP (rel err ~1e-6)
__device__ __forceinline__ float tanh_acc(float u) {
    float e = ex2_fast(u * 2.8853900817779268f);  // exp(2u)
    float r = rcp_fast(e + 1.0f);
    return fmaf(-2.0f, r, 1.0f);
}

__global__ __launch_bounds__(THREADS, 7)
void ferro_kernel(const float* __restrict__ x,
                  const float* __restrict__ k,
                  const float* __restrict__ Ec,
                  const float* __restrict__ Ps,
                  const float* __restrict__ bias,
                  const float* __restrict__ coef,
                  const float* __restrict__ out_bias,
                  float* __restrict__ out)
{
    __shared__ float4 pk[NT];                 // {k, 5Ec, 0.9kEc, 0.1kEc}
    __shared__ float  pw[NT];                 // Ps*coef
    __shared__ float  xs[CIN * RG_H * RG_W];  // x tile with halo
    __shared__ float  red[THREADS];

    const int tid = threadIdx.x;
    const int bx  = blockIdx.x;
    const int sub = bx & 7;                   // 8 sub-tiles: 4 vertical x 2 horizontal
    const int sy  = sub >> 1, sx = sub & 1;
    const int co  = (bx >> 3) & 31;
    const int b   = bx >> 8;
    const int oy0 = sy * TILE_H, ox0 = sx * TILE_W;

    // ---- stage + transform params for this co ----
    const float* kp  = k    + co * NT;
    const float* ep  = Ec   + co * NT;
    const float* pp  = Ps   + co * NT;
    const float* bp  = bias + co * NT;
    const float* cp  = coef + co * NT;
    float part = 0.0f;
    for (int j = tid; j < NT; j += THREADS) {
        float kv = kp[j], ev = ep[j], pv = pp[j], bv = bp[j], cv = cp[j];
        float ke = kv * ev;
        pk[j] = make_float4(kv, 5.0f * ev, 0.9f * ke, 0.1f * ke);
        pw[j] = pv * cv;
        part += bv * cv;
    }
    red[tid] = part;

    // ---- stage x tile (zero-padded halo) ----
    for (int i = tid; i < CIN * RG_H * RG_W; i += THREADS) {
        int cin = i / (RG_H * RG_W);
        int rem = i - cin * (RG_H * RG_W);
        int r   = rem / RG_W;
        int c   = rem - r * RG_W;
        int gy  = oy0 - 1 + r;
        int gx  = ox0 - 1 + c;
        float v = 0.0f;
        if ((unsigned)gy < (unsigned)HW && (unsigned)gx < (unsigned)HW)
            v = x[((b * CIN + cin) * HW + gy) * HW + gx];
        xs[i] = v;
    }
    __syncthreads();

    // deterministic tree-reduce of sum(bias*coef)
    #pragma unroll
    for (int s = THREADS / 2; s > 0; s >>= 1) {
        if (tid < s) red[tid] += red[tid + s];
        __syncthreads();
    }

    const int ty = tid >> 4;      // 0..7
    const int tx = tid & 15;      // 0..15

    float acc = red[0] + __ldg(out_bias + co);

    for (int cin = 0; cin < CIN; ++cin) {
        const float* xb = xs + cin * (RG_H * RG_W) + ty * RG_W + tx;
        const int jb = cin * 27;
        #pragma unroll
        for (int kh = 0; kh < 3; ++kh) {
            #pragma unroll
            for (int kw = 0; kw < 3; ++kw) {
                const float xv  = xb[kh * RG_W + kw];
                const int   tap = kh * 3 + kw;
                #pragma unroll
                for (int kkk = 0; kkk < 3; ++kkk) {
                    const int j = jb + kkk * 9 + tap;
                    float4 p = pk[j];
                    float  w = pw[j];
                    float g = tanh_fast(fmaf(5.0f, xv, p.y));        // gate
                    float u = fmaf(p.w, g, fmaf(p.x, xv, p.z));      // k*x + 0.9kEc + 0.1kEc*g
                    float t = tanh_acc(u);
                    acc = fmaf(w, t, acc);
                }
            }
        }
    }

    const int oy = oy0 + ty, ox = ox0 + tx;
    out[((b * COUT + co) * HW + oy) * HW + ox] = acc;
}

extern "C" void kernel_launch(void* const* d_in, const int* in_sizes, int n_in,
                              void* d_out, int out_size)
{
    const float* x        = (const float*)d_in[0];
    const float* k        = (const float*)d_in[1];
    const float* Ec       = (const float*)d_in[2];
    const float* Ps       = (const float*)d_in[3];
    const float* bias     = (const float*)d_in[4];
    const float* coef     = (const float*)d_in[5];
    const float* out_bias = (const float*)d_in[6];
    float* out = (float*)d_out;

    // grid: 4 batches * 32 cout * 8 spatial sub-tiles = 1024 blocks (single wave @ occ 7)
    ferro_kernel<<<4 * 32 * 8, THREADS>>>(x, k, Ec, Ps, bias, coef, out_bias, out);
}

// round 4
// speedup vs baseline: 1.2525x; 1.2525x over previous
#include <cuda_runtime.h>

// FerroelectricBasisConv2d — GB300 sm_103a, round 2 (resubmit after infra failure)
// Simplified math (stop_gradient makes is_moving_up == 0.5):
//   g = tanh(5x + 5Ec)
//   u = k * (x + Ec * (0.9 + 0.1*g))
//   out = sum( Ps*coef * tanh(u) ) + sum(bias*coef) + out_bias
// Both tanh via HW MUFU.TANH (2 MUFU/term, was 3) — MUFU is the binding pipe.
// Params packed {k, 5Ec, Ec, Ps*coef} -> single broadcast LDS.128 per term.

#define CIN     16
#define COUT    32
#define HW      32
#define NT      432          // CIN * 3 * 9
#define TILE_H  8
#define TILE_W  16
#define RG_H    10           // TILE_H + 2 halo
#define RG_W    18           // TILE_W + 2 halo
#define THREADS 128

__device__ __forceinline__ float tanh_fast(float x) {
    float r; asm("tanh.approx.f32 %0, %1;" : "=f"(r) : "f"(x)); return r;
}

__global__ __launch_bounds__(THREADS, 7)
void ferro_kernel(const float* __restrict__ x,
                  const float* __restrict__ k,
                  const float* __restrict__ Ec,
                  const float* __restrict__ Ps,
                  const float* __restrict__ bias,
                  const float* __restrict__ coef,
                  const float* __restrict__ out_bias,
                  float* __restrict__ out)
{
    __shared__ float4 pk[NT];                 // {k, 5Ec, Ec, Ps*coef}
    __shared__ float  xs[CIN * RG_H * RG_W];  // x tile with halo
    __shared__ float  red[THREADS];

    const int tid = threadIdx.x;
    const int bx  = blockIdx.x;
    const int sub = bx & 7;                   // 8 sub-tiles: 4 vertical x 2 horizontal
    const int sy  = sub >> 1, sx = sub & 1;
    const int co  = (bx >> 3) & 31;
    const int b   = bx >> 8;
    const int oy0 = sy * TILE_H, ox0 = sx * TILE_W;

    // ---- stage + transform params for this co ----
    const float* kp  = k    + co * NT;
    const float* ep  = Ec   + co * NT;
    const float* pp  = Ps   + co * NT;
    const float* bp  = bias + co * NT;
    const float* cp  = coef + co * NT;
    float part = 0.0f;
    for (int j = tid; j < NT; j += THREADS) {
        float kv = kp[j], ev = ep[j], pv = pp[j], bv = bp[j], cv = cp[j];
        pk[j] = make_float4(kv, 5.0f * ev, ev, pv * cv);
        part += bv * cv;
    }
    red[tid] = part;

    // ---- stage x tile (zero-padded halo) ----
    for (int i = tid; i < CIN * RG_H * RG_W; i += THREADS) {
        int cin = i / (RG_H * RG_W);
        int rem = i - cin * (RG_H * RG_W);
        int r   = rem / RG_W;
        int c   = rem - r * RG_W;
        int gy  = oy0 - 1 + r;
        int gx  = ox0 - 1 + c;
        float v = 0.0f;
        if ((unsigned)gy < (unsigned)HW && (unsigned)gx < (unsigned)HW)
            v = x[((b * CIN + cin) * HW + gy) * HW + gx];
        xs[i] = v;
    }
    __syncthreads();

    // deterministic tree-reduce of sum(bias*coef)
    #pragma unroll
    for (int s = THREADS / 2; s > 0; s >>= 1) {
        if (tid < s) red[tid] += red[tid + s];
        __syncthreads();
    }

    const int ty = tid >> 4;      // 0..7
    const int tx = tid & 15;      // 0..15

    float acc = red[0] + __ldg(out_bias + co);

    for (int cin = 0; cin < CIN; ++cin) {
        const float* xb = xs + cin * (RG_H * RG_W) + ty * RG_W + tx;
        const int jb = cin * 27;
        #pragma unroll
        for (int kh = 0; kh < 3; ++kh) {
            #pragma unroll
            for (int kw = 0; kw < 3; ++kw) {
                const float xv  = xb[kh * RG_W + kw];
                const int   tap = kh * 3 + kw;
                #pragma unroll
                for (int kkk = 0; kkk < 3; ++kkk) {
                    const int j = jb + kkk * 9 + tap;
                    float4 p = pk[j];
                    float g = tanh_fast(fmaf(5.0f, xv, p.y));   // gate = tanh(5x+5Ec)
                    float m = fmaf(0.1f, g, 0.9f);              // branch momentum
                    float s = fmaf(p.z, m, xv);                 // x + Ec*m
                    float t = tanh_fast(p.x * s);               // tanh(k * shifted_x)
                    acc = fmaf(p.w, t, acc);                    // += Ps*coef * t
                }
            }
        }
    }

    const int oy = oy0 + ty, ox = ox0 + tx;
    out[((b * COUT + co) * HW + oy) * HW + ox] = acc;
}

extern "C" void kernel_launch(void* const* d_in, const int* in_sizes, int n_in,
                              void* d_out, int out_size)
{
    const float* x        = (const float*)d_in[0];
    const float* k        = (const float*)d_in[1];
    const float* Ec       = (const float*)d_in[2];
    const float* Ps       = (const float*)d_in[3];
    const float* bias     = (const float*)d_in[4];
    const float* coef     = (const float*)d_in[5];
    const float* out_bias = (const float*)d_in[6];
    float* out = (float*)d_out;

    // grid: 4 batches * 32 cout * 8 spatial sub-tiles = 1024 blocks (single wave @ occ 7)
    ferro_kernel<<<4 * 32 * 8, THREADS>>>(x, k, Ec, Ps, bias, coef, out_bias, out);
}